// round 5
// baseline (speedup 1.0000x reference)
#include <cuda_runtime.h>
#include <cuda_bf16.h>
#include <math.h>
#include <stdint.h>

// Problem constants
#define Bn   64
#define Td   256
#define Tp   1024
#define NB   (Bn * 256)
#define NEGV (-1e9f)
#define AL   __align__(256)

// ---------------- device scratch ----------------
__device__ AL __nv_bfloat16 g_F1h[Td * Tp];
__device__ AL __nv_bfloat16 g_F2h[Tp * Td];
__device__ AL __nv_bfloat16 g_Xph[Bn * Tp * 128], g_Xpl[Bn * Tp * 128];
__device__ AL __nv_bfloat16 g_Xsh[Bn * Td * 128], g_Xsl[Bn * Td * 128];
__device__ AL __nv_bfloat16 g_Wp1h[384 * 128], g_Wp1l[384 * 128];
__device__ AL __nv_bfloat16 g_Wp2h[384 * 128], g_Wp2l[384 * 128];
__device__ AL float g_bp1[384], g_bp2[384];
__device__ AL __nv_bfloat16 g_Wodh[128 * 128], g_Wodl[128 * 128];
__device__ AL __nv_bfloat16 g_Woph[128 * 128], g_Wopl[128 * 128];
__device__ AL float g_P1[Bn * Tp * 384];
__device__ AL float g_P2[Bn * Td * 384];
__device__ AL __nv_bfloat16 g_KV1th[NB * Tp], g_KV1tl[NB * Tp];
__device__ AL __nv_bfloat16 g_KV2th[NB * Td], g_KV2tl[NB * Td];
__device__ AL float g_base1[NB], g_base2[NB];   // interleaved: [b*256 + 2d + {0,1}]
__device__ AL __nv_bfloat16 g_Y1h[Bn * Td * 128], g_Y1l[Bn * Td * 128];
__device__ AL __nv_bfloat16 g_Y2h[Bn * Tp * 128], g_Y2l[Bn * Tp * 128];
__device__ AL unsigned g_ob1[Bn * 128], g_ob2[Bn * 128];

// ---------------- helpers ----------------
__device__ __forceinline__ unsigned f2key(float f) {
    unsigned u = __float_as_uint(f);
    return (u & 0x80000000u) ? ~u : (u | 0x80000000u);
}
__device__ __forceinline__ float key2f(unsigned u) {
    unsigned b = (u & 0x80000000u) ? (u ^ 0x80000000u) : ~u;
    return __uint_as_float(b);
}
__device__ __forceinline__ void mma16816(float* d, const uint32_t* a,
                                         uint32_t b0, uint32_t b1) {
    asm volatile(
        "mma.sync.aligned.m16n8k16.row.col.f32.bf16.bf16.f32 "
        "{%0,%1,%2,%3}, {%4,%5,%6,%7}, {%8,%9}, {%0,%1,%2,%3};"
        : "+f"(d[0]), "+f"(d[1]), "+f"(d[2]), "+f"(d[3])
        : "r"(a[0]), "r"(a[1]), "r"(a[2]), "r"(a[3]), "r"(b0), "r"(b1));
}
__device__ __forceinline__ void ldsm4(uint32_t* r, const __nv_bfloat16* p) {
    uint32_t a = (uint32_t)__cvta_generic_to_shared(p);
    asm volatile("ldmatrix.sync.aligned.m8n8.x4.shared.b16 {%0,%1,%2,%3}, [%4];"
                 : "=r"(r[0]), "=r"(r[1]), "=r"(r[2]), "=r"(r[3]) : "r"(a));
}

// ---------------- bf16 GEMM, fused epilogues ----------------
// C[M,N] = sum of A_ta @ B_tb^T (skipping ta=1&tb=1).
// MODE 0: write fp32 C (+bias).  inF0=bias, outF=C, ldx=ldc.
// MODE 1: fused AFT y: acc pairs are (num,den); y=sigmoid(q)*(num+bs)/(den+bs);
//         write bf16 hi/lo Y. inF0=P(q src), inF1=base, outH/outL=Y. (N interleaved 2d/2d+1)
// MODE 2: fused masked max: atomicMax(ob[b*128+col], z) over rows with mask.
//         inI=mask, outU=ob, ldx=SEQ.
template <int TA, int TB, int MODE>
__global__ __launch_bounds__(256, 1) void gemm_bf(
    const __nv_bfloat16* __restrict__ A0, const __nv_bfloat16* __restrict__ A1,
    const __nv_bfloat16* __restrict__ B0, const __nv_bfloat16* __restrict__ B1,
    const float* __restrict__ inF0, const float* __restrict__ inF1,
    const int* __restrict__ inI,
    float* __restrict__ outF, __nv_bfloat16* __restrict__ outH,
    __nv_bfloat16* __restrict__ outL, unsigned* __restrict__ outU,
    int K, int lda, int ldb, int ldx)
{
    __shared__ __nv_bfloat16 SA[TA][128 * 32];
    __shared__ __nv_bfloat16 SB[TB][128 * 32];

    const int tid  = threadIdx.x;
    const int lane = tid & 31;
    const int wid  = tid >> 5;
    const int wm   = (wid >> 1) * 32;
    const int wn   = (wid & 1) * 64;
    const int brow = blockIdx.y * 128;
    const int bcol = blockIdx.x * 128;

    const int lr  = tid >> 2;
    const int lc  = tid & 3;
    const int so0 = lr * 32 + ((lc ^ ((lr >> 1) & 3)) * 8);
    const int so1 = (lr + 64) * 32 + ((lc ^ (((lr + 64) >> 1) & 3)) * 8);

    const __nv_bfloat16* gA0 = A0 + (size_t)(brow + lr) * lda + lc * 8;
    const __nv_bfloat16* gA1 = (TA > 1) ? (A1 + (size_t)(brow + lr) * lda + lc * 8) : A0;
    const __nv_bfloat16* gB0 = B0 + (size_t)(bcol + lr) * ldb + lc * 8;
    const __nv_bfloat16* gB1 = (TB > 1) ? (B1 + (size_t)(bcol + lr) * ldb + lc * 8) : B0;
    const size_t a64 = (size_t)64 * lda, b64 = (size_t)64 * ldb;

    uint4 ra0[2], ra1[2], rb0[2], rb1[2];
    ra0[0] = *(const uint4*)(gA0); ra0[1] = *(const uint4*)(gA0 + a64);
    if (TA > 1) { ra1[0] = *(const uint4*)(gA1); ra1[1] = *(const uint4*)(gA1 + a64); }
    rb0[0] = *(const uint4*)(gB0); rb0[1] = *(const uint4*)(gB0 + b64);
    if (TB > 1) { rb1[0] = *(const uint4*)(gB1); rb1[1] = *(const uint4*)(gB1 + b64); }

    float acc[2][8][4] = {};

    const int arow_b = (lane & 7) + ((lane >> 3) & 1) * 8;
    const int achk_b = (lane >> 4);
    const int brow_b = (lane & 7) + (lane >> 4) * 8;
    const int bchk_b = (lane >> 3) & 1;

    for (int k0 = 0; k0 < K; k0 += 32) {
        *(uint4*)&SA[0][so0] = ra0[0]; *(uint4*)&SA[0][so1] = ra0[1];
        if (TA > 1) { *(uint4*)&SA[1][so0] = ra1[0]; *(uint4*)&SA[1][so1] = ra1[1]; }
        *(uint4*)&SB[0][so0] = rb0[0]; *(uint4*)&SB[0][so1] = rb0[1];
        if (TB > 1) { *(uint4*)&SB[1][so0] = rb1[0]; *(uint4*)&SB[1][so1] = rb1[1]; }
        __syncthreads();

        if (k0 + 32 < K) {
            ra0[0] = *(const uint4*)(gA0 + k0 + 32);
            ra0[1] = *(const uint4*)(gA0 + a64 + k0 + 32);
            if (TA > 1) {
                ra1[0] = *(const uint4*)(gA1 + k0 + 32);
                ra1[1] = *(const uint4*)(gA1 + a64 + k0 + 32);
            }
            rb0[0] = *(const uint4*)(gB0 + k0 + 32);
            rb0[1] = *(const uint4*)(gB0 + b64 + k0 + 32);
            if (TB > 1) {
                rb1[0] = *(const uint4*)(gB1 + k0 + 32);
                rb1[1] = *(const uint4*)(gB1 + b64 + k0 + 32);
            }
        }

        #pragma unroll
        for (int ck = 0; ck < 2; ck++) {
            uint32_t af[TA][2][4];
            #pragma unroll
            for (int mt = 0; mt < 2; mt++) {
                int row = wm + mt * 16 + arow_b;
                int chk = 2 * ck + achk_b;
                int off = row * 32 + ((chk ^ ((row >> 1) & 3)) * 8);
                ldsm4(af[0][mt], &SA[0][off]);
                if (TA > 1) ldsm4(af[TA - 1][mt], &SA[TA - 1][off]);
            }
            #pragma unroll
            for (int ntp = 0; ntp < 4; ntp++) {
                int row = wn + ntp * 16 + brow_b;
                int chk = 2 * ck + bchk_b;
                int off = row * 32 + ((chk ^ ((row >> 1) & 3)) * 8);
                uint32_t bf0[4], bf1[4];
                ldsm4(bf0, &SB[0][off]);
                if (TB > 1) ldsm4(bf1, &SB[TB - 1][off]);
                #pragma unroll
                for (int mt = 0; mt < 2; mt++) {
                    mma16816(acc[mt][2 * ntp],     af[0][mt], bf0[0], bf0[1]);
                    mma16816(acc[mt][2 * ntp + 1], af[0][mt], bf0[2], bf0[3]);
                    if (TB > 1) {
                        mma16816(acc[mt][2 * ntp],     af[0][mt], bf1[0], bf1[1]);
                        mma16816(acc[mt][2 * ntp + 1], af[0][mt], bf1[2], bf1[3]);
                    }
                    if (TA > 1) {
                        mma16816(acc[mt][2 * ntp],     af[TA - 1][mt], bf0[0], bf0[1]);
                        mma16816(acc[mt][2 * ntp + 1], af[TA - 1][mt], bf0[2], bf0[3]);
                    }
                }
            }
        }
        __syncthreads();
    }

    const int g = lane >> 2;
    const int c = lane & 3;

    if (MODE == 0) {
        #pragma unroll
        for (int mt = 0; mt < 2; mt++) {
            #pragma unroll
            for (int nt = 0; nt < 8; nt++) {
                int row = brow + wm + mt * 16 + g;
                int col = bcol + wn + nt * 8 + 2 * c;
                float bx = inF0 ? inF0[col] : 0.f;
                float by = inF0 ? inF0[col + 1] : 0.f;
                float2 v0, v1;
                v0.x = acc[mt][nt][0] + bx; v0.y = acc[mt][nt][1] + by;
                v1.x = acc[mt][nt][2] + bx; v1.y = acc[mt][nt][3] + by;
                *(float2*)&outF[(size_t)row * ldx + col]       = v0;
                *(float2*)&outF[(size_t)(row + 8) * ldx + col] = v1;
            }
        }
    } else if (MODE == 1) {
        // acc pair = (num, den) for (row, d). col = b*256 + 2d.
        const int M = gridDim.y * 128;
        const int b = bcol >> 8;
        #pragma unroll
        for (int mt = 0; mt < 2; mt++) {
            #pragma unroll
            for (int nt = 0; nt < 8; nt++) {
                int row = brow + wm + mt * 16 + g;
                int col = bcol + wn + nt * 8 + 2 * c;
                int d = (col & 255) >> 1;
                float2 bs = *(const float2*)&inF1[col];
                #pragma unroll
                for (int r2 = 0; r2 < 2; r2++) {
                    int rr = row + 8 * r2;
                    float num = acc[mt][nt][2 * r2]     + bs.x;
                    float den = acc[mt][nt][2 * r2 + 1] + bs.y;
                    float q = inF0[((size_t)b * M + rr) * 384 + 256 + d];
                    float sg = 1.f / (1.f + expf(-q));
                    float y = sg * num / den;
                    __nv_bfloat16 h = __float2bfloat16(y);
                    size_t o = ((size_t)b * M + rr) * 128 + d;
                    outH[o] = h;
                    outL[o] = __float2bfloat16(y - __bfloat162float(h));
                }
            }
        }
    } else {
        // masked max over rows, atomicMax into ob[b*128+col]
        const int SEQ = ldx;
        const int b = brow / SEQ;
        int msk[2][2];
        #pragma unroll
        for (int mt = 0; mt < 2; mt++) {
            msk[mt][0] = inI[brow + wm + mt * 16 + g];
            msk[mt][1] = inI[brow + wm + mt * 16 + g + 8];
        }
        #pragma unroll
        for (int nt = 0; nt < 8; nt++) {
            float m0 = -3.0e38f, m1 = -3.0e38f;
            #pragma unroll
            for (int mt = 0; mt < 2; mt++) {
                if (msk[mt][0]) { m0 = fmaxf(m0, acc[mt][nt][0]); m1 = fmaxf(m1, acc[mt][nt][1]); }
                if (msk[mt][1]) { m0 = fmaxf(m0, acc[mt][nt][2]); m1 = fmaxf(m1, acc[mt][nt][3]); }
            }
            #pragma unroll
            for (int off = 4; off < 32; off <<= 1) {
                m0 = fmaxf(m0, __shfl_xor_sync(0xffffffffu, m0, off));
                m1 = fmaxf(m1, __shfl_xor_sync(0xffffffffu, m1, off));
            }
            if (g == 0) {
                int col = wn + nt * 8 + 2 * c;   // bcol==0 for N=128
                if (m0 > -2.9e38f) atomicMax(&outU[b * 128 + col],     f2key(m0));
                if (m1 > -2.9e38f) atomicMax(&outU[b * 128 + col + 1], f2key(m1));
            }
        }
    }
}

// ---------------- small kernels ----------------
__global__ void k_init(unsigned* ob1, unsigned* ob2, float* base1, float* base2) {
    int i = blockIdx.x * 256 + threadIdx.x;
    if (i < Bn * 128) {
        unsigned k = f2key(NEGV);
        ob1[i] = k; ob2[i] = k;
    }
    if (i < NB) { base1[i] = 0.f; base2[i] = 0.f; }
}

__global__ void k_expf(const float* __restrict__ pb, __nv_bfloat16* __restrict__ F1,
                       __nv_bfloat16* __restrict__ F2) {
    __shared__ float s[32][33];
    int j0 = blockIdx.x * 32, i0 = blockIdx.y * 32;
    int tx = threadIdx.x & 31, ty = threadIdx.x >> 5;
    #pragma unroll
    for (int r = ty; r < 32; r += 8) {
        float v = expf(pb[(i0 + r) * 1024 + j0 + tx]) - 1.0f;
        F1[(i0 + r) * Tp + j0 + tx] = __float2bfloat16(v);
        s[r][tx] = v;
    }
    __syncthreads();
    #pragma unroll
    for (int r = ty; r < 32; r += 8)
        F2[(j0 + r) * Td + i0 + tx] = __float2bfloat16(s[tx][r]);
}

// fp32 -> (hi,lo) bf16 split; 8 floats per thread, 16B stores
__global__ void k_split(const float* __restrict__ x, __nv_bfloat16* __restrict__ h,
                        __nv_bfloat16* __restrict__ l, int n8) {
    int i = blockIdx.x * 256 + threadIdx.x;
    if (i >= n8) return;
    float4 v0 = ((const float4*)x)[2 * i];
    float4 v1 = ((const float4*)x)[2 * i + 1];
    float f[8] = {v0.x, v0.y, v0.z, v0.w, v1.x, v1.y, v1.z, v1.w};
    uint32_t hh[4], ll[4];
    #pragma unroll
    for (int j = 0; j < 4; j++) {
        __nv_bfloat162 hp, lp;
        hp.x = __float2bfloat16(f[2 * j]);
        hp.y = __float2bfloat16(f[2 * j + 1]);
        lp.x = __float2bfloat16(f[2 * j]     - __bfloat162float(hp.x));
        lp.y = __float2bfloat16(f[2 * j + 1] - __bfloat162float(hp.y));
        hh[j] = *(uint32_t*)&hp;
        ll[j] = *(uint32_t*)&lp;
    }
    ((uint4*)h)[i] = make_uint4(hh[0], hh[1], hh[2], hh[3]);
    ((uint4*)l)[i] = make_uint4(ll[0], ll[1], ll[2], ll[3]);
}

__global__ void k_pack_split(const float* __restrict__ Wk, const float* __restrict__ bk,
                             const float* __restrict__ Wv, const float* __restrict__ bv,
                             const float* __restrict__ Wq, const float* __restrict__ bq,
                             __nv_bfloat16* __restrict__ Wh, __nv_bfloat16* __restrict__ Wl,
                             float* __restrict__ bp) {
    int i = blockIdx.x * 256 + threadIdx.x;
    if (i < 384 * 128) {
        int r = i >> 7, c = i & 127;
        const float* s = (r < 128) ? Wk : ((r < 256) ? Wv : Wq);
        float w = s[(r & 127) * 128 + c];
        __nv_bfloat16 h = __float2bfloat16(w);
        Wh[i] = h;
        Wl[i] = __float2bfloat16(w - __bfloat162float(h));
    }
    if (i < 384) bp[i] = (i < 128) ? bk[i] : ((i < 256) ? bv[i - 128] : bq[i - 256]);
}

// Build KV transposed (INTERLEAVED rows: b*256 + 2d + {0=ev,1=e}) + fp32 column sums
template <int SEQ>
__global__ __launch_bounds__(256) void k_buildKVt(const float* __restrict__ P,
        const int* __restrict__ mask, __nv_bfloat16* __restrict__ KVh,
        __nv_bfloat16* __restrict__ KVl, float* __restrict__ base) {
    __shared__ float s_ev[32][129];
    __shared__ float s_e[32][129];
    int b = blockIdx.x, j0 = blockIdx.y * 32, t = threadIdx.x;
    #pragma unroll
    for (int i = 0; i < 16; i++) {
        int idx = t + 256 * i;
        int j = idx >> 7, d = idx & 127;
        size_t prow = ((size_t)b * SEQ + j0 + j) * 384;
        float kp = P[prow + d];
        float vp = P[prow + 128 + d];
        float m  = (float)mask[b * SEQ + j0 + j];
        float e  = m * expf(kp);
        s_ev[j][d] = e * vp;
        s_e[j][d]  = e;
    }
    __syncthreads();
    {
        float s = 0.f;
        if (t < 128) {
            for (int j = 0; j < 32; j++) s += s_ev[j][t];
            atomicAdd(&base[b * 256 + 2 * t], s);
        } else {
            for (int j = 0; j < 32; j++) s += s_e[j][t - 128];
            atomicAdd(&base[b * 256 + 2 * (t - 128) + 1], s);
        }
    }
    #pragma unroll
    for (int i = 0; i < 16; i++) {
        int idx = t + 256 * i;
        int d = idx >> 5, j = idx & 31;
        float v1 = s_ev[j][d], v2 = s_e[j][d];
        size_t o1 = ((size_t)(b * 256 + 2 * d)) * SEQ + j0 + j;
        size_t o2 = ((size_t)(b * 256 + 2 * d + 1)) * SEQ + j0 + j;
        __nv_bfloat16 h1 = __float2bfloat16(v1), h2 = __float2bfloat16(v2);
        KVh[o1] = h1; KVl[o1] = __float2bfloat16(v1 - __bfloat162float(h1));
        KVh[o2] = h2; KVl[o2] = __float2bfloat16(v2 - __bfloat162float(h2));
    }
}

__global__ void k_out(const unsigned* __restrict__ ob1, const unsigned* __restrict__ ob2,
                      const float* __restrict__ bpd, const float* __restrict__ bpp,
                      float* __restrict__ out) {
    int i = blockIdx.x * 256 + threadIdx.x;
    if (i < Bn * 128) {
        int t = i & 127;
        out[i]            = key2f(ob1[i]) + bpd[t];
        out[Bn * 128 + i] = key2f(ob2[i]) + bpp[t];
    }
}

// ---------------- launch ----------------
#define SYM(p, s) cudaGetSymbolAddress((void**)&p, s)
#define NUL_F (const float*)0
#define NUL_I (const int*)0
#define NUL_H (__nv_bfloat16*)0

extern "C" void kernel_launch(void* const* d_in, const int* in_sizes, int n_in,
                              void* d_out, int out_size) {
    const float* smiles  = (const float*)d_in[0];
    const float* protein = (const float*)d_in[1];
    const int*   smask   = (const int*)d_in[2];
    const int*   pmask   = (const int*)d_in[3];
    const float* pb      = (const float*)d_in[4];
    const float* Wqd = (const float*)d_in[5],  *bqd = (const float*)d_in[6];
    const float* Wkp = (const float*)d_in[7],  *bkp = (const float*)d_in[8];
    const float* Wvp = (const float*)d_in[9],  *bvp = (const float*)d_in[10];
    const float* Wqp = (const float*)d_in[11], *bqp = (const float*)d_in[12];
    const float* Wkd = (const float*)d_in[13], *bkd = (const float*)d_in[14];
    const float* Wvd = (const float*)d_in[15], *bvd = (const float*)d_in[16];
    const float* Wpd = (const float*)d_in[17], *bpd = (const float*)d_in[18];
    const float* Wpp = (const float*)d_in[19], *bpp = (const float*)d_in[20];
    float* out = (float*)d_out;

    __nv_bfloat16 *F1h, *F2h, *Xph, *Xpl, *Xsh, *Xsl, *Wp1h, *Wp1l, *Wp2h, *Wp2l;
    __nv_bfloat16 *Wodh, *Wodl, *Woph, *Wopl, *KV1th, *KV1tl, *KV2th, *KV2tl;
    __nv_bfloat16 *Y1h, *Y1l, *Y2h, *Y2l;
    float *bp1, *bp2, *P1, *P2, *base1, *base2;
    unsigned *ob1, *ob2;
    SYM(F1h, g_F1h);   SYM(F2h, g_F2h);
    SYM(Xph, g_Xph);   SYM(Xpl, g_Xpl);   SYM(Xsh, g_Xsh);   SYM(Xsl, g_Xsl);
    SYM(Wp1h, g_Wp1h); SYM(Wp1l, g_Wp1l); SYM(Wp2h, g_Wp2h); SYM(Wp2l, g_Wp2l);
    SYM(bp1, g_bp1);   SYM(bp2, g_bp2);
    SYM(Wodh, g_Wodh); SYM(Wodl, g_Wodl); SYM(Woph, g_Woph); SYM(Wopl, g_Wopl);
    SYM(P1, g_P1);     SYM(P2, g_P2);
    SYM(KV1th, g_KV1th); SYM(KV1tl, g_KV1tl); SYM(KV2th, g_KV2th); SYM(KV2tl, g_KV2tl);
    SYM(base1, g_base1); SYM(base2, g_base2);
    SYM(Y1h, g_Y1h);   SYM(Y1l, g_Y1l);   SYM(Y2h, g_Y2h);   SYM(Y2l, g_Y2l);
    SYM(ob1, g_ob1);   SYM(ob2, g_ob2);

    // init + batch-independent precompute
    k_init<<<NB / 256, 256>>>(ob1, ob2, base1, base2);
    k_expf<<<dim3(Tp / 32, Td / 32), 256>>>(pb, F1h, F2h);
    k_split<<<(Bn * Tp * 128 / 8 + 255) / 256, 256>>>(protein, Xph, Xpl, Bn * Tp * 128 / 8);
    k_split<<<(Bn * Td * 128 / 8 + 255) / 256, 256>>>(smiles, Xsh, Xsl, Bn * Td * 128 / 8);
    k_split<<<(128 * 128 / 8 + 255) / 256, 256>>>(Wpd, Wodh, Wodl, 128 * 128 / 8);
    k_split<<<(128 * 128 / 8 + 255) / 256, 256>>>(Wpp, Woph, Wopl, 128 * 128 / 8);
    k_pack_split<<<192, 256>>>(Wkp, bkp, Wvp, bvp, Wqp, bqp, Wp1h, Wp1l, bp1);
    k_pack_split<<<192, 256>>>(Wkd, bkd, Wvd, bvd, Wqd, bqd, Wp2h, Wp2l, bp2);

    // fused projections: [k; v; q]
    gemm_bf<2, 2, 0><<<dim3(3, (Bn * Tp) / 128), 256>>>(
        Xph, Xpl, Wp1h, Wp1l, bp1, NUL_F, NUL_I, P1, NUL_H, NUL_H, (unsigned*)0,
        128, 128, 128, 384);
    gemm_bf<2, 2, 0><<<dim3(3, (Bn * Td) / 128), 256>>>(
        Xsh, Xsl, Wp2h, Wp2l, bp2, NUL_F, NUL_I, P2, NUL_H, NUL_H, (unsigned*)0,
        128, 128, 128, 384);

    // build interleaved transposed KV + exact column-sum base
    k_buildKVt<Tp><<<dim3(Bn, Tp / 32), 256>>>(P1, pmask, KV1th, KV1tl, base1);
    k_buildKVt<Td><<<dim3(Bn, Td / 32), 256>>>(P2, smask, KV2th, KV2tl, base2);

    // main AFT GEMMs with fused y-epilogue (writes Y bf16 hi/lo directly)
    gemm_bf<1, 2, 1><<<dim3(NB / 128, Td / 128), 256>>>(
        F1h, NUL_H, KV1th, KV1tl, P2, base1, NUL_I, (float*)0, Y1h, Y1l, (unsigned*)0,
        Tp, Tp, Tp, 0);
    gemm_bf<1, 2, 1><<<dim3(NB / 128, Tp / 128), 256>>>(
        F2h, NUL_H, KV2th, KV2tl, P1, base2, NUL_I, (float*)0, Y2h, Y2l, (unsigned*)0,
        Td, Td, Td, 0);

    // output projections with fused masked-max epilogue
    gemm_bf<2, 2, 2><<<dim3(1, (Bn * Td) / 128), 256>>>(
        Y1h, Y1l, Wodh, Wodl, NUL_F, NUL_F, smask, (float*)0, NUL_H, NUL_H, ob1,
        128, 128, 128, Td);
    gemm_bf<2, 2, 2><<<dim3(1, (Bn * Tp) / 128), 256>>>(
        Y2h, Y2l, Woph, Wopl, NUL_F, NUL_F, pmask, (float*)0, NUL_H, NUL_H, ob2,
        128, 128, 128, Tp);

    // decode + add output bias
    k_out<<<(Bn * 128 + 255) / 256, 256>>>(ob1, ob2, bpd, bpp, out);
}